// round 6
// baseline (speedup 1.0000x reference)
#include <cuda_runtime.h>
#include <cuda_bf16.h>
#include <cstdint>

#define B_ROWS   65536
#define OUT_N    2048
#define IN_K     64
#define BM       128
#define BN       128
#define NTHREADS 256
#define NT       4              // col tiles per CTA
#define BUFSTR   33792          // C buffer stride: 32 KB tile + 1 KB aux

// ---------------- scratch (__device__ globals: allocation-free) ----------------
// X chunks [Xh, Xl]; C chunks [Ch, Cl]. Products: Ch*Xh + Cl*Xh + Ch*Xl.
__device__ __nv_bfloat16 g_X[2ull * B_ROWS * IN_K];
__device__ __nv_bfloat16 g_C[2ull * OUT_N * IN_K];
__device__ float g_x2[B_ROWS];
__device__ float g_c2[OUT_N];
__device__ float g_e2[OUT_N];      // -exp(-2*log_sigma) * log2(e)

// ---------------- PTX helpers (sm_80-era only) ----------------
__device__ __forceinline__ uint32_t smem_u32(const void* p) {
    uint32_t a;
    asm("{ .reg .u64 t; cvta.to.shared.u64 t, %1; cvt.u32.u64 %0, t; }" : "=r"(a) : "l"(p));
    return a;
}
__device__ __forceinline__ void cp16(uint32_t s, const void* g) {
    asm volatile("{ .reg .u64 ga; cvta.to.global.u64 ga, %1; cp.async.cg.shared.global [%0], [ga], 16; }"
                 :: "r"(s), "l"(g) : "memory");
}
#define CP_COMMIT() asm volatile("cp.async.commit_group;" ::: "memory")
#define CP_WAIT1()  asm volatile("cp.async.wait_group 1;" ::: "memory")

#define LDSM4(r, a) \
    asm volatile("ldmatrix.sync.aligned.m8n8.x4.shared.b16 {%0,%1,%2,%3}, [%4];" \
        : "=r"((r)[0]), "=r"((r)[1]), "=r"((r)[2]), "=r"((r)[3]) : "r"(a))

#define MMA16816(d, a, b0, b1) \
    asm volatile("mma.sync.aligned.m16n8k16.row.col.f32.bf16.bf16.f32 " \
        "{%0,%1,%2,%3}, {%4,%5,%6,%7}, {%8,%9}, {%0,%1,%2,%3};" \
        : "+f"((d)[0]), "+f"((d)[1]), "+f"((d)[2]), "+f"((d)[3]) \
        : "r"((a)[0]), "r"((a)[1]), "r"((a)[2]), "r"((a)[3]), "r"(b0), "r"(b1))

// ---------------- merged prep: fp32 -> (hi, lo) bf16 split + norms ----------------
__global__ void prep_all(const float* __restrict__ inp,
                         const float* __restrict__ cen,
                         const float* __restrict__ ls) {
    const int b = blockIdx.x;
    const bool is_c = (b >= 4096);
    const int g = (is_c ? (b - 4096) : b) * blockDim.x + threadIdx.x;
    const int row = g >> 4, seg = g & 15;

    const float* src = is_c ? cen : inp;
    const float4 v = *(const float4*)(src + (size_t)row * IN_K + seg * 4);
    float vv[4] = {v.x, v.y, v.z, v.w};
    float s = 0.f;
    __nv_bfloat16 h[4], l[4];
    #pragma unroll
    for (int i = 0; i < 4; i++) {
        s = fmaf(vv[i], vv[i], s);
        h[i] = __float2bfloat16(vv[i]);
        l[i] = __float2bfloat16(vv[i] - __bfloat162float(h[i]));
    }
    uint2 hp, lp;
    memcpy(&hp, h, 8); memcpy(&lp, l, 8);
    const size_t base = (size_t)row * IN_K + seg * 4;
    if (is_c) {
        const size_t CH = (size_t)OUT_N * IN_K;
        *(uint2*)(g_C + base)      = hp;
        *(uint2*)(g_C + CH + base) = lp;
    } else {
        const size_t CH = (size_t)B_ROWS * IN_K;
        *(uint2*)(g_X + base)      = hp;
        *(uint2*)(g_X + CH + base) = lp;
    }
    #pragma unroll
    for (int m = 1; m <= 8; m <<= 1) s += __shfl_xor_sync(~0u, s, m);
    if (seg == 0) {
        if (is_c) {
            g_c2[row] = s;
            g_e2[row] = -1.4426950408889634f * expf(-2.f * ls[row]);
        } else {
            g_x2[row] = s;
        }
    }
}

// ---------------- main: persistent row-tile, double-buffered C pipeline ----------------
// smem layout (byte offsets):
//   0        sX  : 2 chunks x [128][64] bf16 (swizzled)     32768
//   32768    buf0: C tile 32768 + c2 512 + e2 512           33792
//   66560    buf1: same                                      33792
//   100352   x2s : 128 floats                                  512
#define SMEM_MAIN 100864

extern __shared__ char smem_raw[];

__global__ __launch_bounds__(NTHREADS, 2)
void rbf_hmma(float* __restrict__ out) {
    const int tid = threadIdx.x;
    const int bid = blockIdx.x;
    const int row0 = (bid >> 2) * BM;
    const int ct0  = (bid & 3) * NT;        // first col tile index

    const uint32_t sb  = smem_u32(smem_raw);
    const uint32_t sXu = sb;
    float* x2s = (float*)(smem_raw + 100352);

    // ---- C tile loader (32 KB tile + 1 KB aux into buf) ----
    auto load_C = [&](int ct, int buf) {
        const uint32_t dst = sb + 32768 + buf * BUFSTR;
        #pragma unroll
        for (int i = 0; i < 8; i++) {
            int u = tid + i * NTHREADS;          // 0..2047
            int ch = u >> 10, rem = u & 1023;
            int r = rem >> 3, c = rem & 7;
            cp16(dst + ch * 16384 + r * 128 + ((c ^ (r & 7)) << 4),
                 g_C + (size_t)ch * (OUT_N * IN_K) + (size_t)(ct * BN + r) * IN_K + c * 8);
        }
        if (tid < 32)
            cp16(dst + 32768 + tid * 16, g_c2 + ct * BN + tid * 4);
        else if (tid < 64)
            cp16(dst + 32768 + 512 + (tid - 32) * 16, g_e2 + ct * BN + (tid - 32) * 4);
    };

    // ---- prologue: X tile + x2 + C0 (group 0), C1 (group 1) ----
    #pragma unroll
    for (int i = 0; i < 8; i++) {
        int u = tid + i * NTHREADS;
        int ch = u >> 10, rem = u & 1023;
        int r = rem >> 3, c = rem & 7;
        cp16(sXu + ch * 16384 + r * 128 + ((c ^ (r & 7)) << 4),
             g_X + (size_t)ch * (B_ROWS * IN_K) + (size_t)(row0 + r) * IN_K + c * 8);
    }
    if (tid < 32) cp16(sb + 100352 + tid * 16, g_x2 + row0 + tid * 4);
    load_C(ct0, 0);
    CP_COMMIT();
    load_C(ct0 + 1, 1);
    CP_COMMIT();

    // ---- warp tiling: 8 warps = 4 (M) x 2 (N); warp tile 32x64 ----
    const int l   = tid & 31;
    const int wid = tid >> 5;
    const int wr  = wid & 3;
    const int wc  = wid >> 2;

    uint32_t abase[2];
    {
        int hb = l >> 4;
        #pragma unroll
        for (int mi = 0; mi < 2; mi++) {
            int row = wr * 32 + mi * 16 + (l & 15);
            abase[mi] = row * 128 + ((hb ^ (row & 7)) << 4);
        }
    }
    uint32_t bbase[4];
    {
        int m = l >> 3;
        int hb = m & 1;
        #pragma unroll
        for (int q = 0; q < 4; q++) {
            int n = wc * 64 + (2 * q + (m >> 1)) * 8 + (l & 7);
            bbase[q] = n * 128 + ((hb ^ (n & 7)) << 4);
        }
    }

    #pragma unroll 1
    for (int t = 0; t < NT; t++) {
        const int buf = t & 1;
        const uint32_t cbuf = sb + 32768 + buf * BUFSTR;
        const int col0 = (ct0 + t) * BN;

        CP_WAIT1();                 // current buf's load complete
        __syncthreads();

        float acc[2][8][4];
        #pragma unroll
        for (int mi = 0; mi < 2; mi++)
            #pragma unroll
            for (int j = 0; j < 8; j++)
                #pragma unroll
                for (int q = 0; q < 4; q++) acc[mi][j][q] = 0.f;

        // 12 k16 steps = 3 chunk-pair phases x 4:
        //   ph0: Xh*Ch, ph1: Xh*Cl, ph2: Xl*Ch
        #pragma unroll
        for (int ks = 0; ks < 12; ks++) {
            const int ph = ks >> 2;
            const uint32_t coA = (ph == 2) ? 16384u : 0u;
            const uint32_t coB = (ph == 1) ? 16384u : 0u;
            const uint32_t kx = (uint32_t)(ks & 3) << 5;

            uint32_t a[2][4], b[4][4];
            LDSM4(a[0], sXu + coA + (abase[0] ^ kx));
            LDSM4(a[1], sXu + coA + (abase[1] ^ kx));
            LDSM4(b[0], cbuf + coB + (bbase[0] ^ kx));
            LDSM4(b[1], cbuf + coB + (bbase[1] ^ kx));
            LDSM4(b[2], cbuf + coB + (bbase[2] ^ kx));
            LDSM4(b[3], cbuf + coB + (bbase[3] ^ kx));

            #pragma unroll
            for (int j = 0; j < 8; j++) {
                uint32_t b0 = b[j >> 1][(j & 1) * 2];
                uint32_t b1 = b[j >> 1][(j & 1) * 2 + 1];
                MMA16816(acc[0][j], a[0], b0, b1);
                MMA16816(acc[1][j], a[1], b0, b1);
            }
        }

        // ---- epilogue: out = exp2((x2 - 2*dot + c2) * e2) ----
        const float* c2s = (const float*)(smem_raw + 32768 + buf * BUFSTR + 32768);
        const float* e2s = c2s + 128;
        #pragma unroll
        for (int mi = 0; mi < 2; mi++) {
            const int rl = wr * 32 + mi * 16 + (l >> 2);
            const float x2a = x2s[rl];
            const float x2b = x2s[rl + 8];
            float* o0 = out + (size_t)(row0 + rl) * OUT_N + col0;
            float* o1 = o0 + 8 * OUT_N;
            #pragma unroll
            for (int j = 0; j < 8; j++) {
                const int c = wc * 64 + j * 8 + 2 * (l & 3);
                const float c20 = c2s[c],  c21 = c2s[c + 1];
                const float e0  = e2s[c],  e1  = e2s[c + 1];
                const float* A  = acc[mi][j];
                float s0 = fmaxf(fmaf(-2.f, A[0], x2a + c20), 0.f);
                float s1 = fmaxf(fmaf(-2.f, A[1], x2a + c21), 0.f);
                float s2 = fmaxf(fmaf(-2.f, A[2], x2b + c20), 0.f);
                float s3 = fmaxf(fmaf(-2.f, A[3], x2b + c21), 0.f);
                *(float2*)(o0 + c) = make_float2(exp2f(s0 * e0), exp2f(s1 * e1));
                *(float2*)(o1 + c) = make_float2(exp2f(s2 * e0), exp2f(s3 * e1));
            }
        }

        __syncthreads();            // all reads of buf done before overwrite
        if (t + 2 < NT) load_C(ct0 + t + 2, buf);
        CP_COMMIT();                // empty group when nothing issued (keeps count)
    }
}

extern "C" void kernel_launch(void* const* d_in, const int* in_sizes, int n_in,
                              void* d_out, int out_size) {
    (void)in_sizes; (void)n_in; (void)out_size;
    const float* input      = (const float*)d_in[0];
    const float* centers    = (const float*)d_in[1];
    const float* log_sigmas = (const float*)d_in[2];
    float* out              = (float*)d_out;

    cudaFuncSetAttribute(rbf_hmma, cudaFuncAttributeMaxDynamicSharedMemorySize, SMEM_MAIN);

    prep_all<<<B_ROWS * 16 / 256 + OUT_N * 16 / 256, 256>>>(input, centers, log_sigmas);
    rbf_hmma<<<(B_ROWS / BM) * (OUT_N / BN / NT), NTHREADS, SMEM_MAIN>>>(out);
}

// round 7
// speedup vs baseline: 1.9265x; 1.9265x over previous
#include <cuda_runtime.h>
#include <cuda_fp16.h>
#include <cstdint>

#define B_ROWS   65536
#define OUT_N    2048
#define IN_K     64
#define BM       128
#define BN       128
#define NTHREADS 256
#define NT       4              // col tiles per CTA
#define BUFSTR   17408          // C buffer stride: 16 KB tile + 1 KB aux

// ---------------- scratch (__device__ globals: allocation-free) ----------------
// Single-pass fp16: dot ~= fp16(x) . fp16(c), fp32 accumulate.
__device__ __half g_X[(size_t)B_ROWS * IN_K];
__device__ __half g_C[(size_t)OUT_N * IN_K];
__device__ float g_x2[B_ROWS];     // exact ||x||^2 (fp32)
__device__ float g_c2[OUT_N];      // exact ||c||^2 (fp32)
__device__ float g_e2[OUT_N];      // -exp(-2*log_sigma) * log2(e)

// ---------------- PTX helpers (sm_80-era only) ----------------
__device__ __forceinline__ uint32_t smem_u32(const void* p) {
    uint32_t a;
    asm("{ .reg .u64 t; cvta.to.shared.u64 t, %1; cvt.u32.u64 %0, t; }" : "=r"(a) : "l"(p));
    return a;
}
__device__ __forceinline__ void cp16(uint32_t s, const void* g) {
    asm volatile("{ .reg .u64 ga; cvta.to.global.u64 ga, %1; cp.async.cg.shared.global [%0], [ga], 16; }"
                 :: "r"(s), "l"(g) : "memory");
}
#define CP_COMMIT() asm volatile("cp.async.commit_group;" ::: "memory")
#define CP_WAIT1()  asm volatile("cp.async.wait_group 1;" ::: "memory")

#define LDSM4(r, a) \
    asm volatile("ldmatrix.sync.aligned.m8n8.x4.shared.b16 {%0,%1,%2,%3}, [%4];" \
        : "=r"((r)[0]), "=r"((r)[1]), "=r"((r)[2]), "=r"((r)[3]) : "r"(a))

#define MMA16816(d, a, b0, b1) \
    asm volatile("mma.sync.aligned.m16n8k16.row.col.f32.f16.f16.f32 " \
        "{%0,%1,%2,%3}, {%4,%5,%6,%7}, {%8,%9}, {%0,%1,%2,%3};" \
        : "+f"((d)[0]), "+f"((d)[1]), "+f"((d)[2]), "+f"((d)[3]) \
        : "r"((a)[0]), "r"((a)[1]), "r"((a)[2]), "r"((a)[3]), "r"(b0), "r"(b1))

// ---------------- prep: fp32 -> fp16 + exact norms ----------------
// blocks [0, 4096): input rows; blocks [4096, 4224): center rows.
__global__ void prep_all(const float* __restrict__ inp,
                         const float* __restrict__ cen,
                         const float* __restrict__ ls) {
    const int b = blockIdx.x;
    const bool is_c = (b >= 4096);
    const int g = (is_c ? (b - 4096) : b) * blockDim.x + threadIdx.x;
    const int row = g >> 4, seg = g & 15;

    const float* src = is_c ? cen : inp;
    const float4 v = *(const float4*)(src + (size_t)row * IN_K + seg * 4);
    float vv[4] = {v.x, v.y, v.z, v.w};
    float s = 0.f;
    __half h[4];
    #pragma unroll
    for (int i = 0; i < 4; i++) {
        s = fmaf(vv[i], vv[i], s);
        h[i] = __float2half_rn(vv[i]);
    }
    uint2 hp;
    memcpy(&hp, h, 8);
    const size_t base = (size_t)row * IN_K + seg * 4;
    if (is_c) *(uint2*)(g_C + base) = hp;
    else      *(uint2*)(g_X + base) = hp;

    #pragma unroll
    for (int m = 1; m <= 8; m <<= 1) s += __shfl_xor_sync(~0u, s, m);
    if (seg == 0) {
        if (is_c) {
            g_c2[row] = s;
            g_e2[row] = -1.4426950408889634f * expf(-2.f * ls[row]);
        } else {
            g_x2[row] = s;
        }
    }
}

// ---------------- main: persistent row-tile, double-buffered C pipeline ----------------
// smem layout (byte offsets):
//   0      sX  : [128][64] fp16 swizzled                    16384
//   16384  buf0: C tile 16384 + c2 512 + e2 512             17408
//   33792  buf1: same                                        17408
//   51200  x2s : 128 floats                                    512
#define SMEM_MAIN 51712

extern __shared__ char smem_raw[];

__global__ __launch_bounds__(NTHREADS, 2)
void rbf_hmma(float* __restrict__ out) {
    const int tid = threadIdx.x;
    const int bid = blockIdx.x;
    const int row0 = (bid >> 2) * BM;
    const int ct0  = (bid & 3) * NT;        // first col tile index

    const uint32_t sb  = smem_u32(smem_raw);
    const uint32_t sXu = sb;
    float* x2s = (float*)(smem_raw + 51200);

    // ---- C tile loader (16 KB tile + 1 KB aux into buf) ----
    auto load_C = [&](int ct, int buf) {
        const uint32_t dst = sb + 16384 + buf * BUFSTR;
        #pragma unroll
        for (int i = 0; i < 4; i++) {
            int u = tid + i * NTHREADS;          // 0..1023
            int r = u >> 3, c = u & 7;
            cp16(dst + r * 128 + ((c ^ (r & 7)) << 4),
                 g_C + (size_t)(ct * BN + r) * IN_K + c * 8);
        }
        if (tid < 32)
            cp16(dst + 16384 + tid * 16, g_c2 + ct * BN + tid * 4);
        else if (tid < 64)
            cp16(dst + 16384 + 512 + (tid - 32) * 16, g_e2 + ct * BN + (tid - 32) * 4);
    };

    // ---- prologue: X tile + x2 + C0 (group 0), C1 (group 1) ----
    #pragma unroll
    for (int i = 0; i < 4; i++) {
        int u = tid + i * NTHREADS;
        int r = u >> 3, c = u & 7;
        cp16(sXu + r * 128 + ((c ^ (r & 7)) << 4),
             g_X + (size_t)(row0 + r) * IN_K + c * 8);
    }
    if (tid < 32) cp16(sb + 51200 + tid * 16, g_x2 + row0 + tid * 4);
    load_C(ct0, 0);
    CP_COMMIT();
    load_C(ct0 + 1, 1);
    CP_COMMIT();

    // ---- warp tiling: 8 warps = 4 (M) x 2 (N); warp tile 32x64 ----
    const int l   = tid & 31;
    const int wid = tid >> 5;
    const int wr  = wid & 3;
    const int wc  = wid >> 2;

    uint32_t abase[2];
    {
        int hb = l >> 4;
        #pragma unroll
        for (int mi = 0; mi < 2; mi++) {
            int row = wr * 32 + mi * 16 + (l & 15);
            abase[mi] = row * 128 + ((hb ^ (row & 7)) << 4);
        }
    }
    uint32_t bbase[4];
    {
        int m = l >> 3;
        int hb = m & 1;
        #pragma unroll
        for (int q = 0; q < 4; q++) {
            int n = wc * 64 + (2 * q + (m >> 1)) * 8 + (l & 7);
            bbase[q] = n * 128 + ((hb ^ (n & 7)) << 4);
        }
    }

    #pragma unroll 1
    for (int t = 0; t < NT; t++) {
        const int buf = t & 1;
        const uint32_t cbuf = sb + 16384 + buf * BUFSTR;
        const int col0 = (ct0 + t) * BN;

        CP_WAIT1();                 // current buf's load complete
        __syncthreads();

        float acc[2][8][4];
        #pragma unroll
        for (int mi = 0; mi < 2; mi++)
            #pragma unroll
            for (int j = 0; j < 8; j++)
                #pragma unroll
                for (int q = 0; q < 4; q++) acc[mi][j][q] = 0.f;

        // single fp16 pass: 4 k16 steps over K=64
        #pragma unroll
        for (int ks = 0; ks < 4; ks++) {
            const uint32_t kx = (uint32_t)ks << 5;   // XOR in swizzled 16B-unit space

            uint32_t a[2][4], b[4][4];
            LDSM4(a[0], sXu + (abase[0] ^ kx));
            LDSM4(a[1], sXu + (abase[1] ^ kx));
            LDSM4(b[0], cbuf + (bbase[0] ^ kx));
            LDSM4(b[1], cbuf + (bbase[1] ^ kx));
            LDSM4(b[2], cbuf + (bbase[2] ^ kx));
            LDSM4(b[3], cbuf + (bbase[3] ^ kx));

            #pragma unroll
            for (int j = 0; j < 8; j++) {
                uint32_t b0 = b[j >> 1][(j & 1) * 2];
                uint32_t b1 = b[j >> 1][(j & 1) * 2 + 1];
                MMA16816(acc[0][j], a[0], b0, b1);
                MMA16816(acc[1][j], a[1], b0, b1);
            }
        }

        // ---- epilogue: out = exp2((x2 - 2*dot + c2) * e2) ----
        const float* c2s = (const float*)(smem_raw + 16384 + buf * BUFSTR + 16384);
        const float* e2s = c2s + 128;
        #pragma unroll
        for (int mi = 0; mi < 2; mi++) {
            const int rl = wr * 32 + mi * 16 + (l >> 2);
            const float x2a = x2s[rl];
            const float x2b = x2s[rl + 8];
            float* o0 = out + (size_t)(row0 + rl) * OUT_N + col0;
            float* o1 = o0 + 8 * OUT_N;
            #pragma unroll
            for (int j = 0; j < 8; j++) {
                const int c = wc * 64 + j * 8 + 2 * (l & 3);
                const float c20 = c2s[c],  c21 = c2s[c + 1];
                const float e0  = e2s[c],  e1  = e2s[c + 1];
                const float* A  = acc[mi][j];
                float s0 = fmaxf(fmaf(-2.f, A[0], x2a + c20), 0.f);
                float s1 = fmaxf(fmaf(-2.f, A[1], x2a + c21), 0.f);
                float s2 = fmaxf(fmaf(-2.f, A[2], x2b + c20), 0.f);
                float s3 = fmaxf(fmaf(-2.f, A[3], x2b + c21), 0.f);
                *(float2*)(o0 + c) = make_float2(exp2f(s0 * e0), exp2f(s1 * e1));
                *(float2*)(o1 + c) = make_float2(exp2f(s2 * e0), exp2f(s3 * e1));
            }
        }

        __syncthreads();            // all reads of buf done before overwrite
        if (t + 2 < NT) load_C(ct0 + t + 2, buf);
        CP_COMMIT();                // keep group count aligned
    }
}

extern "C" void kernel_launch(void* const* d_in, const int* in_sizes, int n_in,
                              void* d_out, int out_size) {
    (void)in_sizes; (void)n_in; (void)out_size;
    const float* input      = (const float*)d_in[0];
    const float* centers    = (const float*)d_in[1];
    const float* log_sigmas = (const float*)d_in[2];
    float* out              = (float*)d_out;

    cudaFuncSetAttribute(rbf_hmma, cudaFuncAttributeMaxDynamicSharedMemorySize, SMEM_MAIN);

    prep_all<<<B_ROWS * 16 / 256 + OUT_N * 16 / 256, 256>>>(input, centers, log_sigmas);
    rbf_hmma<<<(B_ROWS / BM) * (OUT_N / BN / NT), NTHREADS, SMEM_MAIN>>>(out);
}